// round 8
// baseline (speedup 1.0000x reference)
#include <cuda_runtime.h>

#define KK    64
#define S1C   5
#define CC    128
#define MM    320         // KK*S1C
#define PP    1936        // 44*44
#define NN    8
#define PT    128         // pixels per tile
#define TILES 16          // ceil(1936/128)
#define ALPHA_C 1500.0f
#define EPS_C   1e-12f

// ---- device scratch (static: no allocations allowed) ----
// g_w layout: pair P = chunk*80 + s*16 + mg packs rows (k, k+16), k = chunk*32 + mg:
//   g_w[P*256 + c*2 + 0] = 2a*cent[(chunk*32+mg)*5 + s][c]
//   g_w[P*256 + c*2 + 1] = 2a*cent[(chunk*32+mg+16)*5 + s][c]
__device__ float g_w[160 * 256];
__device__ float g_b[MM];                       // [P*2 + j]
__device__ float g_part[NN * TILES * KK * CC];  // per-tile partial accumulators (4.2 MB)
__device__ float g_sumw[NN * TILES * KK];

// ---- f32x2 helpers (ptxas never auto-emits FFMA2; B300 fma pipe is 2x wider via f32x2) ----
__device__ __forceinline__ unsigned long long dup2(float v) {
    unsigned long long r;
    asm("mov.b64 %0, {%1, %1};" : "=l"(r) : "f"(v));
    return r;
}
__device__ __forceinline__ void fma2(unsigned long long& d, unsigned long long a, unsigned long long b) {
    asm("fma.rn.f32x2 %0, %1, %2, %0;" : "+l"(d) : "l"(a), "l"(b));
}
__device__ __forceinline__ float2 unpack2(unsigned long long v) {
    float2 r;
    asm("mov.b64 {%0, %1}, %2;" : "=f"(r.x), "=f"(r.y) : "l"(v));
    return r;
}

// ======================= prep: build interleaved w and b =======================
__global__ void prep_kernel(const float* __restrict__ cent) {
    int m = blockIdx.x * 8 + (threadIdx.x >> 5);
    int lane = threadIdx.x & 31;
    if (m >= MM) return;
    float4 v = *(const float4*)(cent + m * CC + lane * 4);
    float ss = v.x * v.x + v.y * v.y + v.z * v.z + v.w * v.w;
    #pragma unroll
    for (int o = 16; o; o >>= 1) ss += __shfl_xor_sync(0xffffffffu, ss, o);
    int k = m / S1C, s = m % S1C;
    int chunk = k >> 5, kk = k & 31;
    int mg = kk & 15, j = kk >> 4;
    int P = chunk * 80 + s * 16 + mg;
    if (lane == 0) g_b[P * 2 + j] = -ALPHA_C * sqrtf(ss);
    float* wr = g_w + (P * 128 + lane * 4) * 2 + j;
    wr[0] = 2.0f * ALPHA_C * v.x;
    wr[2] = 2.0f * ALPHA_C * v.y;
    wr[4] = 2.0f * ALPHA_C * v.z;
    wr[6] = 2.0f * ALPHA_C * v.w;
}

// ======================= fused main kernel =======================
// block = (n, pixel-tile of 128), 128 blocks = 1 wave. smem 158464 B:
//   xs : [64 c2][130 p][2]  pairs {x[2c2][p], x[2c2+1][p]}    66560 B
//   ws : 80 pairs x 256     one 80 KB w chunk / was alias     81920 B
//   red: [128 p][17]        cross-warp alpha reduction         8704 B
//   bs : float[320]         biases                             1280 B
__global__ __launch_bounds__(512, 1)
void main_kernel(const float* __restrict__ x, float* __restrict__ sa_out) {
    extern __shared__ float smem[];
    float* xs  = smem;                    // 16640 floats
    float* ws  = smem + 16640;            // 20480 floats (alias: was 64x130x2 = 16640)
    float* red = smem + 16640 + 20480;    // 2176 floats
    float* bs  = red + 2176;              // 320 floats
    float* was = ws;

    int tid = threadIdx.x;
    int lane = tid & 31;    // pixel quad base p = 4*lane
    int mg = tid >> 5;      // warp id = k-pair base within chunk
    int bx = blockIdx.x;
    int n = bx >> 4, tile = bx & 15;
    int p0 = tile * PT;
    int pvalid = min(PT, PP - p0);   // 128, or 16 on tile 15 (multiple of 16)

    if (tid < 320) bs[tid] = g_b[tid];

    // ---- load x tile: pair-interleave in registers, STS.128 stores ----
    {
        int r = tid >> 3;            // c2 row (64 rows)
        int seg = (tid & 7) * 16;    // pixel segment
        const float* s0 = x + (n * CC + 2 * r) * PP + p0 + seg;
        const float* s1 = s0 + PP;
        bool ok = seg < pvalid;      // pvalid is 128 or 16; seg multiple of 16
        #pragma unroll
        for (int i = 0; i < 4; i++) {
            float4 a = ok ? *(const float4*)(s0 + i * 4) : make_float4(0.f, 0.f, 0.f, 0.f);
            float4 b = ok ? *(const float4*)(s1 + i * 4) : make_float4(0.f, 0.f, 0.f, 0.f);
            float* d = xs + (r * 130 + seg + i * 4) * 2;
            *(float4*)(d)     = make_float4(a.x, b.x, a.y, b.y);
            *(float4*)(d + 4) = make_float4(a.z, b.z, a.w, b.w);
        }
    }

    // ---- phase 1: logits GEMM (2 chunks of 32 k x 5 s) + register softmax over s ----
    float l0r[16], btr[16];   // idx = ch*8 + k2*4 + px ; k = ch*32 + mg + k2*16
    for (int ch = 0; ch < 2; ch++) {
        __syncthreads();
        {   // stream w chunk (80 KB)
            const float4* wsrc = (const float4*)(g_w + ch * 20480);
            float4* wdst = (float4*)ws;
            #pragma unroll
            for (int i = 0; i < 10; i++) wdst[tid + i * 512] = wsrc[tid + i * 512];
        }
        __syncthreads();

        unsigned long long acc[5][4];
        #pragma unroll
        for (int s = 0; s < 5; s++)
            #pragma unroll
            for (int q = 0; q < 4; q++) acc[s][q] = 0ull;

        #pragma unroll 4
        for (int c2 = 0; c2 < 64; c2++) {
            const float* xr = xs + (c2 * 130 + 4 * lane) * 2;
            float4 xa = *(const float4*)xr;
            float4 xb = *(const float4*)(xr + 4);
            unsigned long long xd0 = dup2(xa.x), xd1 = dup2(xa.y);
            unsigned long long xd2 = dup2(xa.z), xd3 = dup2(xa.w);
            unsigned long long xd4 = dup2(xb.x), xd5 = dup2(xb.y);
            unsigned long long xd6 = dup2(xb.z), xd7 = dup2(xb.w);
            #pragma unroll
            for (int s = 0; s < 5; s++) {
                ulonglong2 wv = *(const ulonglong2*)(ws + (s * 16 + mg) * 256 + c2 * 4);
                fma2(acc[s][0], wv.x, xd0); fma2(acc[s][0], wv.y, xd1);
                fma2(acc[s][1], wv.x, xd2); fma2(acc[s][1], wv.y, xd3);
                fma2(acc[s][2], wv.x, xd4); fma2(acc[s][2], wv.y, xd5);
                fma2(acc[s][3], wv.x, xd6); fma2(acc[s][3], wv.y, xd7);
            }
        }

        float b0[5], b1[5];
        #pragma unroll
        for (int s = 0; s < 5; s++) {
            b0[s] = bs[(ch * 80 + s * 16 + mg) * 2 + 0];
            b1[s] = bs[(ch * 80 + s * 16 + mg) * 2 + 1];
        }
        #pragma unroll
        for (int px = 0; px < 4; px++) {
            float lx[5], ly[5];
            #pragma unroll
            for (int s = 0; s < 5; s++) {
                float2 a = unpack2(acc[s][px]);
                lx[s] = a.x + b0[s];
                ly[s] = a.y + b1[s];
            }
            float m0 = fmaxf(fmaxf(fmaxf(lx[0], lx[1]), fmaxf(lx[2], lx[3])), lx[4]);
            float e0 = __expf(lx[0] - m0);
            float s0 = e0 + __expf(lx[1] - m0) + __expf(lx[2] - m0)
                          + __expf(lx[3] - m0) + __expf(lx[4] - m0);
            l0r[ch * 8 + px] = lx[0];
            btr[ch * 8 + px] = e0 * __frcp_rn(s0);
            float m1 = fmaxf(fmaxf(fmaxf(ly[0], ly[1]), fmaxf(ly[2], ly[3])), ly[4]);
            float e1 = __expf(ly[0] - m1);
            float s1 = e1 + __expf(ly[1] - m1) + __expf(ly[2] - m1)
                          + __expf(ly[3] - m1) + __expf(ly[4] - m1);
            l0r[ch * 8 + 4 + px] = ly[0];
            btr[ch * 8 + 4 + px] = e1 * __frcp_rn(s1);
        }
    }

    // ---- alpha softmax over k: cross-warp reduction via red[p][17] ----
    #pragma unroll
    for (int px = 0; px < 4; px++) {
        float mx = fmaxf(fmaxf(l0r[px], l0r[4 + px]), fmaxf(l0r[8 + px], l0r[12 + px]));
        red[(4 * lane + px) * 17 + mg] = mx;
    }
    __syncthreads();
    float amax[4];
    #pragma unroll
    for (int px = 0; px < 4; px++) {
        float m = -1e30f;
        #pragma unroll
        for (int i = 0; i < 16; i++) m = fmaxf(m, red[(4 * lane + px) * 17 + i]);
        amax[px] = m;
    }
    __syncthreads();
    #pragma unroll
    for (int px = 0; px < 4; px++) {
        float s = __expf(l0r[px] - amax[px]) + __expf(l0r[4 + px] - amax[px])
                + __expf(l0r[8 + px] - amax[px]) + __expf(l0r[12 + px] - amax[px]);
        red[(4 * lane + px) * 17 + mg] = s;
    }
    __syncthreads();
    float ainv[4];
    #pragma unroll
    for (int px = 0; px < 4; px++) {
        float s = 0.f;
        #pragma unroll
        for (int i = 0; i < 16; i++) s += red[(4 * lane + px) * 17 + i];
        ainv[px] = __frcp_rn(s);
    }

    // ---- w_assign to smem (alias over ws), soft_assign to gmem, sumw ----
    #pragma unroll
    for (int ch = 0; ch < 2; ch++)
        #pragma unroll
        for (int k2 = 0; k2 < 2; k2++) {
            int k = ch * 32 + mg + k2 * 16;
            float sav[4];
            float sw = 0.f;
            #pragma unroll
            for (int px = 0; px < 4; px++) {
                int idx = ch * 8 + k2 * 4 + px;
                float sa = __expf(l0r[idx] - amax[px]) * ainv[px] * btr[idx];
                int p = 4 * lane + px;
                float wa = (p < pvalid) ? (1.0f + sa) : 0.0f;
                sav[px] = sa;
                sw += wa;
                *(float2*)(was + (k * 130 + p) * 2) = make_float2(wa, wa);
            }
            if (4 * lane < pvalid)
                *(float4*)(sa_out + (n * KK + k) * PP + p0 + 4 * lane) =
                    make_float4(sav[0], sav[1], sav[2], sav[3]);
            #pragma unroll
            for (int o = 16; o; o >>= 1) sw += __shfl_xor_sync(0xffffffffu, sw, o);
            if (lane == 0) g_sumw[bx * 64 + k] = sw;
        }
    __syncthreads();

    // ---- phase 2: out_part[k][c] = sum_p wa[k][p] * x[c][p] ----
    {
        int cg = lane, kg = mg;   // k = kg*4+q ; c2 = cg and cg+32
        unsigned long long a2[4][2];
        #pragma unroll
        for (int q = 0; q < 4; q++) { a2[q][0] = 0ull; a2[q][1] = 0ull; }
        #pragma unroll 2
        for (int p = 0; p < PT; p += 2) {
            ulonglong2 xv0 = *(const ulonglong2*)(xs + (cg * 130 + p) * 2);
            ulonglong2 xv1 = *(const ulonglong2*)(xs + ((cg + 32) * 130 + p) * 2);
            #pragma unroll
            for (int q = 0; q < 4; q++) {
                ulonglong2 wv = *(const ulonglong2*)(was + ((kg * 4 + q) * 130 + p) * 2);
                fma2(a2[q][0], wv.x, xv0.x);
                fma2(a2[q][0], wv.y, xv0.y);
                fma2(a2[q][1], wv.x, xv1.x);
                fma2(a2[q][1], wv.y, xv1.y);
            }
        }
        float* pb = g_part + bx * 8192;
        #pragma unroll
        for (int q = 0; q < 4; q++) {
            int k = kg * 4 + q;
            #pragma unroll
            for (int j = 0; j < 2; j++) {
                int c2 = cg + 32 * j;
                float2 r = unpack2(a2[q][j]);
                *(float2*)(pb + k * 128 + c2 * 2) = r;
            }
        }
    }
}

// ======================= fused finalize: tile-reduce + rep*sumw + intra-norm + global norm =======================
// grid = 8 (one block per n), block = 1024: thread = (k = tid>>4, 8 c values)
__global__ __launch_bounds__(1024, 1)
void finalize_kernel(const float* __restrict__ cent, float* __restrict__ out) {
    __shared__ float srow[64];
    __shared__ float s_sc;
    int n = blockIdx.x;
    int tid = threadIdx.x;
    int k = tid >> 4, g = tid & 15;
    int c0 = g * 8;

    float4 a0 = make_float4(0.f, 0.f, 0.f, 0.f);
    float4 a1 = make_float4(0.f, 0.f, 0.f, 0.f);
    const float* pb = g_part + (n * TILES) * 8192 + k * 128 + c0;
    #pragma unroll
    for (int t = 0; t < TILES; t++) {
        float4 u0 = *(const float4*)(pb + t * 8192);
        float4 u1 = *(const float4*)(pb + t * 8192 + 4);
        a0.x += u0.x; a0.y += u0.y; a0.z += u0.z; a0.w += u0.w;
        a1.x += u1.x; a1.y += u1.y; a1.z += u1.z; a1.w += u1.w;
    }
    float sw = 0.f;
    const float* sb = g_sumw + n * TILES * 64 + k;
    #pragma unroll
    for (int t = 0; t < TILES; t++) sw += sb[t * 64];

    float4 r0 = *(const float4*)(cent + k * S1C * CC + c0);
    float4 r1 = *(const float4*)(cent + k * S1C * CC + c0 + 4);
    float v[8];
    v[0] = a0.x - r0.x * sw; v[1] = a0.y - r0.y * sw;
    v[2] = a0.z - r0.z * sw; v[3] = a0.w - r0.w * sw;
    v[4] = a1.x - r1.x * sw; v[5] = a1.y - r1.y * sw;
    v[6] = a1.z - r1.z * sw; v[7] = a1.w - r1.w * sw;

    float ss = 0.f;
    #pragma unroll
    for (int i = 0; i < 8; i++) ss += v[i] * v[i];
    #pragma unroll
    for (int o = 8; o; o >>= 1) ss += __shfl_xor_sync(0xffffffffu, ss, o);  // 16-lane group

    float rn = fmaxf(sqrtf(ss), EPS_C);
    if (g == 0) srow[k] = ss / (rn * rn);
    __syncthreads();
    if (tid < 32) {
        float t = srow[tid] + srow[tid + 32];
        #pragma unroll
        for (int o = 16; o; o >>= 1) t += __shfl_xor_sync(0xffffffffu, t, o);
        if (tid == 0) s_sc = 1.0f / fmaxf(sqrtf(t), EPS_C);
    }
    __syncthreads();
    float sc = s_sc / rn;

    float* dst = out + n * (KK * CC) + k * 128 + c0;
    *(float4*)(dst)     = make_float4(v[0] * sc, v[1] * sc, v[2] * sc, v[3] * sc);
    *(float4*)(dst + 4) = make_float4(v[4] * sc, v[5] * sc, v[6] * sc, v[7] * sc);
}

extern "C" void kernel_launch(void* const* d_in, const int* in_sizes, int n_in,
                              void* d_out, int out_size) {
    const float* x    = (const float*)d_in[0];   // (8,128,44,44)
    const float* cent = (const float*)d_in[1];   // (64,5,128)
    float* out = (float*)d_out;                  // [flat (8,8192) | soft_assign (8,64,1,1936)]
    float* sa = out + NN * KK * CC;

    cudaFuncSetAttribute(main_kernel, cudaFuncAttributeMaxDynamicSharedMemorySize, 158464);

    prep_kernel<<<40, 256>>>(cent);
    main_kernel<<<NN * TILES, 512, 158464>>>(x, sa);
    finalize_kernel<<<NN, 1024>>>(cent, out);
}